// round 1
// baseline (speedup 1.0000x reference)
#include <cuda_runtime.h>
#include <math.h>

// Problem constants
#define Dd 1024   // feature dim
#define Cc 1000   // prototypes
#define Bb 128    // batch
#define RT 1128   // Cc + Bb stacked rows

// Scratch (device globals — no allocation allowed)
__device__ float g_Lt[Dd * Dd];        // tril(L)              4 MB
__device__ float g_MA[RT * Dd];        // [mu; x] @ Lt         4.6 MB
__device__ float g_q[RT];              // ||MA_r||^2 + eps*||In_r||^2
__device__ float g_bd[RT];             // beta . In_r
__device__ float g_part[2 * Bb * Dd];  // split-K partial dots (C padded to 1024)

// ---------------------------------------------------------------------------
// 1) Lt = tril(L)
// ---------------------------------------------------------------------------
__global__ __launch_bounds__(256) void tril_kernel(const float* __restrict__ L) {
    int idx = (blockIdx.x * 256 + threadIdx.x) * 4;
    int i = idx >> 10;        // row
    int j = idx & (Dd - 1);   // col
    float4 v = *reinterpret_cast<const float4*>(L + idx);
    float4 o;
    o.x = (j + 0 <= i) ? v.x : 0.f;
    o.y = (j + 1 <= i) ? v.y : 0.f;
    o.z = (j + 2 <= i) ? v.z : 0.f;
    o.w = (j + 3 <= i) ? v.w : 0.f;
    *reinterpret_cast<float4*>(g_Lt + idx) = o;
}

// ---------------------------------------------------------------------------
// 2) MA = [mu; x] @ Lt    (NN gemm, M=1128, N=1024, K=1024)
//    BM=128 BN=64 BK=16, 256 threads, 8x4 micro-tile
// ---------------------------------------------------------------------------
__global__ __launch_bounds__(256) void gemm_ma(const float* __restrict__ x,
                                               const float* __restrict__ mu) {
    const int BM = 128, BN = 64, BK = 16;
    __shared__ float As[BK][BM];   // transposed: [k][m]
    __shared__ float Bs[BK][BN];   // [k][n]

    int bm = blockIdx.x * BM;
    int bn = blockIdx.y * BN;
    int tid = threadIdx.x;
    int tx = tid & 15;   // col group (n = tx*4)
    int ty = tid >> 4;   // row group (m = ty*8)

    float acc[8][4];
#pragma unroll
    for (int i = 0; i < 8; i++)
#pragma unroll
        for (int j = 0; j < 4; j++) acc[i][j] = 0.f;

    for (int k0 = 0; k0 < Dd; k0 += BK) {
        // Load A tile: 128 rows x 16 k  (2 float4 per thread), transposed store
#pragma unroll
        for (int l = 0; l < 2; l++) {
            int s = tid + l * 256;           // 0..511
            int row = s >> 2;                // 0..127
            int kq = (s & 3) * 4;            // 0,4,8,12
            int gr = bm + row;
            float4 v = make_float4(0.f, 0.f, 0.f, 0.f);
            if (gr < RT) {
                const float* src = (gr < Cc) ? (mu + (size_t)gr * Dd)
                                             : (x + (size_t)(gr - Cc) * Dd);
                v = *reinterpret_cast<const float4*>(src + k0 + kq);
            }
            As[kq + 0][row] = v.x;
            As[kq + 1][row] = v.y;
            As[kq + 2][row] = v.z;
            As[kq + 3][row] = v.w;
        }
        // Load B tile: 16 k x 64 n (1 float4 per thread)
        {
            int kr = tid >> 4;               // 0..15
            int n4 = (tid & 15) * 4;         // 0..60
            float4 v = *reinterpret_cast<const float4*>(
                g_Lt + (size_t)(k0 + kr) * Dd + bn + n4);
            *reinterpret_cast<float4*>(&Bs[kr][n4]) = v;
        }
        __syncthreads();

#pragma unroll
        for (int kk = 0; kk < BK; kk++) {
            float a[8], b[4];
#pragma unroll
            for (int i = 0; i < 8; i++) a[i] = As[kk][ty * 8 + i];
#pragma unroll
            for (int j = 0; j < 4; j++) b[j] = Bs[kk][tx * 4 + j];
#pragma unroll
            for (int i = 0; i < 8; i++)
#pragma unroll
                for (int j = 0; j < 4; j++)
                    acc[i][j] = fmaf(a[i], b[j], acc[i][j]);
        }
        __syncthreads();
    }

#pragma unroll
    for (int i = 0; i < 8; i++) {
        int gr = bm + ty * 8 + i;
        if (gr < RT) {
            float4 v = make_float4(acc[i][0], acc[i][1], acc[i][2], acc[i][3]);
            *reinterpret_cast<float4*>(g_MA + (size_t)gr * Dd + bn + tx * 4) = v;
        }
    }
}

// ---------------------------------------------------------------------------
// 3) Row stats: q_r = ||MA_r||^2 + 1e-6*||In_r||^2 ; bd_r = beta . In_r
// ---------------------------------------------------------------------------
__global__ __launch_bounds__(256) void rownorm(const float* __restrict__ x,
                                               const float* __restrict__ mu,
                                               const float* __restrict__ beta) {
    int r = blockIdx.x;
    const float* in = (r < Cc) ? (mu + (size_t)r * Dd) : (x + (size_t)(r - Cc) * Dd);
    const float* ma = g_MA + (size_t)r * Dd;
    int tid = threadIdx.x;

    float4 a4 = *reinterpret_cast<const float4*>(ma + tid * 4);
    float4 v4 = *reinterpret_cast<const float4*>(in + tid * 4);
    float4 b4 = *reinterpret_cast<const float4*>(beta + tid * 4);

    float sma = a4.x * a4.x + a4.y * a4.y + a4.z * a4.z + a4.w * a4.w;
    float sin_ = v4.x * v4.x + v4.y * v4.y + v4.z * v4.z + v4.w * v4.w;
    float sb = b4.x * v4.x + b4.y * v4.y + b4.z * v4.z + b4.w * v4.w;

#pragma unroll
    for (int off = 16; off > 0; off >>= 1) {
        sma += __shfl_xor_sync(0xFFFFFFFFu, sma, off);
        sin_ += __shfl_xor_sync(0xFFFFFFFFu, sin_, off);
        sb += __shfl_xor_sync(0xFFFFFFFFu, sb, off);
    }
    __shared__ float red[3][8];
    int wid = tid >> 5, lane = tid & 31;
    if (lane == 0) { red[0][wid] = sma; red[1][wid] = sin_; red[2][wid] = sb; }
    __syncthreads();
    if (tid == 0) {
        float t0 = 0.f, t1 = 0.f, t2 = 0.f;
#pragma unroll
        for (int w = 0; w < 8; w++) { t0 += red[0][w]; t1 += red[1][w]; t2 += red[2][w]; }
        g_q[r] = t0 + 1e-6f * t1;
        g_bd[r] = t2;
    }
}

// ---------------------------------------------------------------------------
// 4) Cross dots (NT gemm, split over z):
//    z=0: part0[b,c] = A_b . M_c       (rows of g_MA)
//    z=1: part1[b,c] = x_b . mu_c
//    BM=32 (b), BN=64 (c), BK=32, 256 threads, 2x4 micro-tile
// ---------------------------------------------------------------------------
__global__ __launch_bounds__(256) void dot_gemm(const float* __restrict__ x,
                                                const float* __restrict__ mu) {
    const int BM = 32, BN = 64, BK = 32;
    __shared__ float As[BK][BM];
    __shared__ float Bs[BK][BN];

    int z = blockIdx.z;
    int bm = blockIdx.x * BM;   // b offset
    int bn = blockIdx.y * BN;   // c offset
    int tid = threadIdx.x;
    int tx = tid & 15;          // n = tx*4
    int ty = tid >> 4;          // m = ty*2

    float acc[2][4];
#pragma unroll
    for (int i = 0; i < 2; i++)
#pragma unroll
        for (int j = 0; j < 4; j++) acc[i][j] = 0.f;

    for (int k0 = 0; k0 < Dd; k0 += BK) {
        // A tile: 32 rows x 32 k (1 float4/thread)
        {
            int row = tid >> 3;            // 0..31
            int kq = (tid & 7) * 4;        // 0..28
            const float* arow = z ? (x + (size_t)(bm + row) * Dd)
                                  : (g_MA + (size_t)(Cc + bm + row) * Dd);
            float4 v = *reinterpret_cast<const float4*>(arow + k0 + kq);
            As[kq + 0][row] = v.x;
            As[kq + 1][row] = v.y;
            As[kq + 2][row] = v.z;
            As[kq + 3][row] = v.w;
        }
        // B tile: 64 rows x 32 k (2 float4/thread)
#pragma unroll
        for (int l = 0; l < 2; l++) {
            int s = tid + l * 256;
            int row = s >> 3;              // 0..63
            int kq = (s & 7) * 4;
            int gc = bn + row;
            float4 v = make_float4(0.f, 0.f, 0.f, 0.f);
            if (z == 0) {
                // g_MA has RT=1128 rows; gc <= 1023 always valid memory
                v = *reinterpret_cast<const float4*>(g_MA + (size_t)gc * Dd + k0 + kq);
            } else if (gc < Cc) {
                v = *reinterpret_cast<const float4*>(mu + (size_t)gc * Dd + k0 + kq);
            }
            Bs[kq + 0][row] = v.x;
            Bs[kq + 1][row] = v.y;
            Bs[kq + 2][row] = v.z;
            Bs[kq + 3][row] = v.w;
        }
        __syncthreads();

#pragma unroll
        for (int kk = 0; kk < BK; kk++) {
            float a[2], b[4];
            a[0] = As[kk][ty * 2 + 0];
            a[1] = As[kk][ty * 2 + 1];
#pragma unroll
            for (int j = 0; j < 4; j++) b[j] = Bs[kk][tx * 4 + j];
#pragma unroll
            for (int i = 0; i < 2; i++)
#pragma unroll
                for (int j = 0; j < 4; j++)
                    acc[i][j] = fmaf(a[i], b[j], acc[i][j]);
        }
        __syncthreads();
    }

#pragma unroll
    for (int i = 0; i < 2; i++) {
        float4 v = make_float4(acc[i][0], acc[i][1], acc[i][2], acc[i][3]);
        *reinterpret_cast<float4*>(
            g_part + (size_t)z * Bb * Dd + (size_t)(bm + ty * 2 + i) * Dd + bn + tx * 4) = v;
    }
}

// ---------------------------------------------------------------------------
// 5) Finalize: out[b,c] = -scale*(sqrt(quad+eps) + lmbda*sqrt(bd^2+eps))
// ---------------------------------------------------------------------------
__global__ __launch_bounds__(256) void finalize(const float* __restrict__ lmbda,
                                                const float* __restrict__ scale,
                                                float* __restrict__ out) {
    int idx = blockIdx.x * 256 + threadIdx.x;
    if (idx >= Bb * Cc) return;
    int b = idx / Cc;
    int c = idx - b * Cc;
    float s = g_part[(size_t)b * Dd + c] + 1e-6f * g_part[(size_t)Bb * Dd + (size_t)b * Dd + c];
    float quad = g_q[Cc + b] + g_q[c] - 2.f * s;
    float bd = g_bd[Cc + b] - g_bd[c];
    float lm = *lmbda;
    float sc = *scale;
    out[idx] = -sc * (sqrtf(quad + 1e-6f) + lm * sqrtf(bd * bd + 1e-6f));
}

// ---------------------------------------------------------------------------
extern "C" void kernel_launch(void* const* d_in, const int* in_sizes, int n_in,
                              void* d_out, int out_size) {
    const float *x = nullptr, *mu = nullptr, *beta = nullptr, *L = nullptr;
    const float *lmbda = nullptr, *scale = nullptr;
    for (int i = 0; i < n_in; i++) {
        const float* p = (const float*)d_in[i];
        switch (in_sizes[i]) {
            case Bb * Dd:  x = p; break;
            case Cc * Dd:  mu = p; break;
            case Dd:       beta = p; break;
            case Dd * Dd:  L = p; break;
            case 1:        if (!lmbda) lmbda = p; else scale = p; break;
            default: break;
        }
    }

    tril_kernel<<<(Dd * Dd) / (256 * 4), 256>>>(L);
    gemm_ma<<<dim3((RT + 127) / 128, Dd / 64), 256>>>(x, mu);
    rownorm<<<RT, 256>>>(x, mu, beta);
    dot_gemm<<<dim3(Bb / 32, Dd / 64, 2), 256>>>(x, mu);
    finalize<<<(Bb * Cc + 255) / 256, 256>>>(lmbda, scale, (float*)d_out);
}

// round 2
// speedup vs baseline: 1.6089x; 1.6089x over previous
#include <cuda_runtime.h>
#include <math.h>

// Problem constants
#define Dd 1024   // feature dim
#define Cc 1000   // prototypes
#define Bb 128    // batch
#define RT 1128   // Cc + Bb stacked rows
#define KS 8      // split-K factor for cross-dot gemm
#define KC (Dd / KS)

// Scratch (device globals — no allocation allowed)
__device__ float g_MA[RT * Dd];          // [mu; x] @ tril(L)    4.6 MB
__device__ float g_q[RT];                // ||MA_r||^2 + eps*||In_r||^2
__device__ float g_bd[RT];               // beta . In_r
__device__ float g_part[KS * Bb * Dd];   // split-K partial cross dots (c padded to 1024)

// ---------------------------------------------------------------------------
// 1) MA = [mu; x] @ tril(L)   (NN gemm, M=1128, N=1024, K=1024)
//    BM=128 BN=64 BK=16, 256 threads, 8x4 micro-tile, register prefetch.
//    tril applied on the fly to the B tile (no scratch Lt).
// ---------------------------------------------------------------------------
__global__ __launch_bounds__(256) void gemm_ma(const float* __restrict__ x,
                                               const float* __restrict__ mu,
                                               const float* __restrict__ L) {
    const int BK = 16;
    __shared__ __align__(16) float As[BK][132];  // [k][m], BM=128 + pad 4
    __shared__ __align__(16) float Bs[BK][68];   // [k][n], BN=64 + pad 4

    int bm = blockIdx.x * 128;
    int bn = blockIdx.y * 64;
    int tid = threadIdx.x;
    int tx = tid & 15;   // n = tx*4
    int ty = tid >> 4;   // m = ty*8

    // A-load mapping: 2 float4 per thread
    int arow0 = tid >> 2;                 // 0..63
    int akq = (tid & 3) * 4;              // 0,4,8,12
    const float* asrc[2];
    bool avalid[2];
#pragma unroll
    for (int l = 0; l < 2; l++) {
        int row = arow0 + l * 64;
        int gr = bm + row;
        avalid[l] = (gr < RT);
        if (gr < Cc)       asrc[l] = mu + (size_t)gr * Dd + akq;
        else if (gr < RT)  asrc[l] = x + (size_t)(gr - Cc) * Dd + akq;
        else               asrc[l] = x + akq;  // safe dummy
    }
    // B-load mapping: 1 float4 per thread from L, tril-masked at STS
    int bkr = tid >> 4;                   // 0..15 (k row within tile)
    int bn4 = (tid & 15) * 4;             // 0..60
    const float* bsrc = L + (size_t)bkr * Dd + bn + bn4;

    float acc[8][4];
#pragma unroll
    for (int i = 0; i < 8; i++)
#pragma unroll
        for (int j = 0; j < 4; j++) acc[i][j] = 0.f;

    // prefetch k0 = 0
    float4 ra[2], rb;
#pragma unroll
    for (int l = 0; l < 2; l++)
        ra[l] = avalid[l] ? *reinterpret_cast<const float4*>(asrc[l])
                          : make_float4(0.f, 0.f, 0.f, 0.f);
    rb = *reinterpret_cast<const float4*>(bsrc);

    for (int k0 = 0; k0 < Dd; k0 += BK) {
        // store current tile
#pragma unroll
        for (int l = 0; l < 2; l++) {
            int row = arow0 + l * 64;
            As[akq + 0][row] = ra[l].x;
            As[akq + 1][row] = ra[l].y;
            As[akq + 2][row] = ra[l].z;
            As[akq + 3][row] = ra[l].w;
        }
        {
            int krow = k0 + bkr;  // global k of this B row
            float4 m;
            m.x = (bn + bn4 + 0 <= krow) ? rb.x : 0.f;
            m.y = (bn + bn4 + 1 <= krow) ? rb.y : 0.f;
            m.z = (bn + bn4 + 2 <= krow) ? rb.z : 0.f;
            m.w = (bn + bn4 + 3 <= krow) ? rb.w : 0.f;
            *reinterpret_cast<float4*>(&Bs[bkr][bn4]) = m;
        }
        __syncthreads();

        // prefetch next tile while computing
        if (k0 + BK < Dd) {
#pragma unroll
            for (int l = 0; l < 2; l++)
                ra[l] = avalid[l]
                    ? *reinterpret_cast<const float4*>(asrc[l] + k0 + BK)
                    : make_float4(0.f, 0.f, 0.f, 0.f);
            rb = *reinterpret_cast<const float4*>(bsrc + (size_t)(k0 + BK) * Dd);
        }

#pragma unroll
        for (int kk = 0; kk < BK; kk++) {
            float a[8], b[4];
            float4 a0 = *reinterpret_cast<const float4*>(&As[kk][ty * 8]);
            float4 a1 = *reinterpret_cast<const float4*>(&As[kk][ty * 8 + 4]);
            a[0] = a0.x; a[1] = a0.y; a[2] = a0.z; a[3] = a0.w;
            a[4] = a1.x; a[5] = a1.y; a[6] = a1.z; a[7] = a1.w;
            float4 b0 = *reinterpret_cast<const float4*>(&Bs[kk][tx * 4]);
            b[0] = b0.x; b[1] = b0.y; b[2] = b0.z; b[3] = b0.w;
#pragma unroll
            for (int i = 0; i < 8; i++)
#pragma unroll
                for (int j = 0; j < 4; j++)
                    acc[i][j] = fmaf(a[i], b[j], acc[i][j]);
        }
        __syncthreads();
    }

#pragma unroll
    for (int i = 0; i < 8; i++) {
        int gr = bm + ty * 8 + i;
        if (gr < RT) {
            float4 v = make_float4(acc[i][0], acc[i][1], acc[i][2], acc[i][3]);
            *reinterpret_cast<float4*>(g_MA + (size_t)gr * Dd + bn + tx * 4) = v;
        }
    }
}

// ---------------------------------------------------------------------------
// 2) Row stats: q_r = ||MA_r||^2 + 1e-6*||In_r||^2 ; bd_r = beta . In_r
// ---------------------------------------------------------------------------
__global__ __launch_bounds__(256) void rownorm(const float* __restrict__ x,
                                               const float* __restrict__ mu,
                                               const float* __restrict__ beta) {
    int r = blockIdx.x;
    const float* in = (r < Cc) ? (mu + (size_t)r * Dd) : (x + (size_t)(r - Cc) * Dd);
    const float* ma = g_MA + (size_t)r * Dd;
    int tid = threadIdx.x;

    float4 a4 = *reinterpret_cast<const float4*>(ma + tid * 4);
    float4 v4 = *reinterpret_cast<const float4*>(in + tid * 4);
    float4 b4 = *reinterpret_cast<const float4*>(beta + tid * 4);

    float sma = a4.x * a4.x + a4.y * a4.y + a4.z * a4.z + a4.w * a4.w;
    float sin_ = v4.x * v4.x + v4.y * v4.y + v4.z * v4.z + v4.w * v4.w;
    float sb = b4.x * v4.x + b4.y * v4.y + b4.z * v4.z + b4.w * v4.w;

#pragma unroll
    for (int off = 16; off > 0; off >>= 1) {
        sma += __shfl_xor_sync(0xFFFFFFFFu, sma, off);
        sin_ += __shfl_xor_sync(0xFFFFFFFFu, sin_, off);
        sb += __shfl_xor_sync(0xFFFFFFFFu, sb, off);
    }
    __shared__ float red[3][8];
    int wid = tid >> 5, lane = tid & 31;
    if (lane == 0) { red[0][wid] = sma; red[1][wid] = sin_; red[2][wid] = sb; }
    __syncthreads();
    if (tid == 0) {
        float t0 = 0.f, t1 = 0.f, t2 = 0.f;
#pragma unroll
        for (int w = 0; w < 8; w++) { t0 += red[0][w]; t1 += red[1][w]; t2 += red[2][w]; }
        g_q[r] = t0 + 1e-6f * t1;
        g_bd[r] = t2;
    }
}

// ---------------------------------------------------------------------------
// 3) Cross dots: part[ks][b][c] = sum_{k in chunk ks} A_b[k] * M_c[k]
//    (A rows = g_MA rows Cc..Cc+127, M rows = g_MA rows 0..1023)
//    BM=64 BN=64 BK=16, split-K=8, 256 threads, 4x4 micro-tile, reg prefetch.
// ---------------------------------------------------------------------------
__global__ __launch_bounds__(256) void dot_gemm() {
    const int BK = 16;
    __shared__ __align__(16) float As[BK][68];
    __shared__ __align__(16) float Bs[BK][68];

    int bm = blockIdx.x * 64;          // b offset
    int bn = blockIdx.y * 64;          // c offset
    int kb = blockIdx.z * KC;          // k chunk base
    int tid = threadIdx.x;
    int tx = tid & 15;                 // n = tx*4
    int ty = tid >> 4;                 // m = ty*4

    int lrow = tid >> 2;               // 0..63
    int lkq = (tid & 3) * 4;           // 0,4,8,12
    const float* aptr = g_MA + (size_t)(Cc + bm + lrow) * Dd + kb + lkq;
    const float* bptr = g_MA + (size_t)(bn + lrow) * Dd + kb + lkq;

    float acc[4][4];
#pragma unroll
    for (int i = 0; i < 4; i++)
#pragma unroll
        for (int j = 0; j < 4; j++) acc[i][j] = 0.f;

    float4 ra = *reinterpret_cast<const float4*>(aptr);
    float4 rb = *reinterpret_cast<const float4*>(bptr);

#pragma unroll 1
    for (int it = 0; it < KC / BK; it++) {
        As[lkq + 0][lrow] = ra.x;
        As[lkq + 1][lrow] = ra.y;
        As[lkq + 2][lrow] = ra.z;
        As[lkq + 3][lrow] = ra.w;
        Bs[lkq + 0][lrow] = rb.x;
        Bs[lkq + 1][lrow] = rb.y;
        Bs[lkq + 2][lrow] = rb.z;
        Bs[lkq + 3][lrow] = rb.w;
        __syncthreads();

        if (it + 1 < KC / BK) {
            ra = *reinterpret_cast<const float4*>(aptr + (it + 1) * BK);
            rb = *reinterpret_cast<const float4*>(bptr + (it + 1) * BK);
        }

#pragma unroll
        for (int kk = 0; kk < BK; kk++) {
            float4 a = *reinterpret_cast<const float4*>(&As[kk][ty * 4]);
            float4 b = *reinterpret_cast<const float4*>(&Bs[kk][tx * 4]);
            float av[4] = {a.x, a.y, a.z, a.w};
            float bv[4] = {b.x, b.y, b.z, b.w};
#pragma unroll
            for (int i = 0; i < 4; i++)
#pragma unroll
                for (int j = 0; j < 4; j++)
                    acc[i][j] = fmaf(av[i], bv[j], acc[i][j]);
        }
        __syncthreads();
    }

#pragma unroll
    for (int i = 0; i < 4; i++) {
        float4 v = make_float4(acc[i][0], acc[i][1], acc[i][2], acc[i][3]);
        *reinterpret_cast<float4*>(
            g_part + ((size_t)blockIdx.z * Bb + bm + ty * 4 + i) * Dd + bn + tx * 4) = v;
    }
}

// ---------------------------------------------------------------------------
// 4) Finalize: out[b,c] = -scale*(sqrt(quad+eps) + lmbda*sqrt(bd^2+eps))
//    quad = q_b + q_c - 2*sum_ks part[ks][b][c]
//    (epsilon cross-dot term eps*x.mu dropped: contributes ~2e-6 abs vs quad~1e3)
// ---------------------------------------------------------------------------
__global__ __launch_bounds__(256) void finalize(const float* __restrict__ lmbda,
                                                const float* __restrict__ scale,
                                                float* __restrict__ out) {
    int idx = blockIdx.x * 256 + threadIdx.x;
    if (idx >= Bb * Cc) return;
    int b = idx / Cc;
    int c = idx - b * Cc;
    float s = 0.f;
#pragma unroll
    for (int ks = 0; ks < KS; ks++)
        s += g_part[((size_t)ks * Bb + b) * Dd + c];
    float quad = g_q[Cc + b] + g_q[c] - 2.f * s;
    float bd = g_bd[Cc + b] - g_bd[c];
    float lm = *lmbda;
    float sc = *scale;
    out[idx] = -sc * (sqrtf(quad + 1e-6f) + lm * sqrtf(bd * bd + 1e-6f));
}

// ---------------------------------------------------------------------------
extern "C" void kernel_launch(void* const* d_in, const int* in_sizes, int n_in,
                              void* d_out, int out_size) {
    const float *x = nullptr, *mu = nullptr, *beta = nullptr, *L = nullptr;
    const float *lmbda = nullptr, *scale = nullptr;
    for (int i = 0; i < n_in; i++) {
        const float* p = (const float*)d_in[i];
        switch (in_sizes[i]) {
            case Bb * Dd:  x = p; break;
            case Cc * Dd:  mu = p; break;
            case Dd:       beta = p; break;
            case Dd * Dd:  L = p; break;
            case 1:        if (!lmbda) lmbda = p; else scale = p; break;
            default: break;
        }
    }

    gemm_ma<<<dim3((RT + 127) / 128, Dd / 64), 256>>>(x, mu, L);
    rownorm<<<RT, 256>>>(x, mu, beta);
    dot_gemm<<<dim3(Bb / 64, Dd / 64, KS), 256>>>();
    finalize<<<(Bb * Cc + 255) / 256, 256>>>(lmbda, scale, (float*)d_out);
}

// round 3
// speedup vs baseline: 1.7692x; 1.0996x over previous
#include <cuda_runtime.h>
#include <math.h>

// Problem constants
#define Dd 1024   // feature dim
#define Cc 1000   // prototypes
#define Bb 128    // batch
#define RT 1128   // Cc + Bb stacked rows
#define KS 8      // split-K factor for cross-dot gemm
#define KC (Dd / KS)

// Scratch (device globals — no allocation allowed)
__device__ float g_MA[RT * Dd];          // [mu; x] @ tril(L)    4.6 MB
__device__ float g_q[RT];                // ||MA_r||^2 + eps*||In_r||^2
__device__ float g_bd[RT];               // beta . In_r
__device__ float g_part[KS * Bb * Dd];   // split-K partial cross dots (c padded to 1024)

// ---------------------------------------------------------------------------
// 1) MA = [mu; x] @ tril(L)   (NN gemm, M=1128, N=1024, K=1024)
//    TRIANGULAR SKIP: for column tile [bn, bn+64), L[k,n]=0 for k<n, so the
//    K loop starts at k0=bn — halves total FLOPs. BM=64 BN=64 BK=16,
//    256 threads, 4x4 micro-tile, register prefetch. Grid 18x16=288 blocks
//    (~2/SM) so variable-K blocks load-balance across waves.
// ---------------------------------------------------------------------------
__global__ __launch_bounds__(256) void gemm_ma(const float* __restrict__ x,
                                               const float* __restrict__ mu,
                                               const float* __restrict__ L) {
    const int BK = 16;
    __shared__ __align__(16) float As[BK][68];   // [k][m]
    __shared__ __align__(16) float Bs[BK][68];   // [k][n]

    int bm = blockIdx.x * 64;
    int bn = blockIdx.y * 64;
    int tid = threadIdx.x;
    int tx = tid & 15;   // n = tx*4
    int ty = tid >> 4;   // m = ty*4

    // A-load mapping: 1 float4 per thread (64 rows x 16 k)
    int arow = tid >> 2;                  // 0..63
    int akq = (tid & 3) * 4;              // 0,4,8,12
    int gr = bm + arow;
    bool avalid = (gr < RT);
    const float* asrc;
    if (gr < Cc)       asrc = mu + (size_t)gr * Dd + akq;
    else if (gr < RT)  asrc = x + (size_t)(gr - Cc) * Dd + akq;
    else               asrc = mu + akq;   // safe dummy

    // B-load mapping: 1 float4 per thread from L (16 k x 64 n)
    int bkr = tid >> 4;                   // 0..15
    int bn4 = (tid & 15) * 4;             // 0..60
    const float* bsrc = L + (size_t)bkr * Dd + bn + bn4;

    float acc[4][4];
#pragma unroll
    for (int i = 0; i < 4; i++)
#pragma unroll
        for (int j = 0; j < 4; j++) acc[i][j] = 0.f;

    // K starts at bn (tril): everything below is structurally zero.
    int kstart = bn;

    float4 ra, rb;
    ra = avalid ? *reinterpret_cast<const float4*>(asrc + kstart)
                : make_float4(0.f, 0.f, 0.f, 0.f);
    rb = *reinterpret_cast<const float4*>(bsrc + (size_t)kstart * Dd);

    for (int k0 = kstart; k0 < Dd; k0 += BK) {
        As[akq + 0][arow] = ra.x;
        As[akq + 1][arow] = ra.y;
        As[akq + 2][arow] = ra.z;
        As[akq + 3][arow] = ra.w;
        {
            int krow = k0 + bkr;  // global k of this B row
            float4 m;
            m.x = (bn + bn4 + 0 <= krow) ? rb.x : 0.f;
            m.y = (bn + bn4 + 1 <= krow) ? rb.y : 0.f;
            m.z = (bn + bn4 + 2 <= krow) ? rb.z : 0.f;
            m.w = (bn + bn4 + 3 <= krow) ? rb.w : 0.f;
            *reinterpret_cast<float4*>(&Bs[bkr][bn4]) = m;
        }
        __syncthreads();

        // prefetch next tile while computing
        if (k0 + BK < Dd) {
            ra = avalid ? *reinterpret_cast<const float4*>(asrc + k0 + BK)
                        : make_float4(0.f, 0.f, 0.f, 0.f);
            rb = *reinterpret_cast<const float4*>(bsrc + (size_t)(k0 + BK) * Dd);
        }

#pragma unroll
        for (int kk = 0; kk < BK; kk++) {
            float4 a = *reinterpret_cast<const float4*>(&As[kk][ty * 4]);
            float4 b = *reinterpret_cast<const float4*>(&Bs[kk][tx * 4]);
            float av[4] = {a.x, a.y, a.z, a.w};
            float bv[4] = {b.x, b.y, b.z, b.w};
#pragma unroll
            for (int i = 0; i < 4; i++)
#pragma unroll
                for (int j = 0; j < 4; j++)
                    acc[i][j] = fmaf(av[i], bv[j], acc[i][j]);
        }
        __syncthreads();
    }

#pragma unroll
    for (int i = 0; i < 4; i++) {
        int go = bm + ty * 4 + i;
        if (go < RT) {
            float4 v = make_float4(acc[i][0], acc[i][1], acc[i][2], acc[i][3]);
            *reinterpret_cast<float4*>(g_MA + (size_t)go * Dd + bn + tx * 4) = v;
        }
    }
}

// ---------------------------------------------------------------------------
// 2) Row stats: q_r = ||MA_r||^2 + 1e-6*||In_r||^2 ; bd_r = beta . In_r
// ---------------------------------------------------------------------------
__global__ __launch_bounds__(256) void rownorm(const float* __restrict__ x,
                                               const float* __restrict__ mu,
                                               const float* __restrict__ beta) {
    int r = blockIdx.x;
    const float* in = (r < Cc) ? (mu + (size_t)r * Dd) : (x + (size_t)(r - Cc) * Dd);
    const float* ma = g_MA + (size_t)r * Dd;
    int tid = threadIdx.x;

    float4 a4 = *reinterpret_cast<const float4*>(ma + tid * 4);
    float4 v4 = *reinterpret_cast<const float4*>(in + tid * 4);
    float4 b4 = *reinterpret_cast<const float4*>(beta + tid * 4);

    float sma = a4.x * a4.x + a4.y * a4.y + a4.z * a4.z + a4.w * a4.w;
    float sin_ = v4.x * v4.x + v4.y * v4.y + v4.z * v4.z + v4.w * v4.w;
    float sb = b4.x * v4.x + b4.y * v4.y + b4.z * v4.z + b4.w * v4.w;

#pragma unroll
    for (int off = 16; off > 0; off >>= 1) {
        sma += __shfl_xor_sync(0xFFFFFFFFu, sma, off);
        sin_ += __shfl_xor_sync(0xFFFFFFFFu, sin_, off);
        sb += __shfl_xor_sync(0xFFFFFFFFu, sb, off);
    }
    __shared__ float red[3][8];
    int wid = tid >> 5, lane = tid & 31;
    if (lane == 0) { red[0][wid] = sma; red[1][wid] = sin_; red[2][wid] = sb; }
    __syncthreads();
    if (tid == 0) {
        float t0 = 0.f, t1 = 0.f, t2 = 0.f;
#pragma unroll
        for (int w = 0; w < 8; w++) { t0 += red[0][w]; t1 += red[1][w]; t2 += red[2][w]; }
        g_q[r] = t0 + 1e-6f * t1;
        g_bd[r] = t2;
    }
}

// ---------------------------------------------------------------------------
// 3) Cross dots: part[ks][b][c] = sum_{k in chunk ks} A_b[k] * M_c[k]
//    BM=64 BN=64 BK=16, split-K=8, 256 threads, 4x4 micro-tile, reg prefetch.
// ---------------------------------------------------------------------------
__global__ __launch_bounds__(256) void dot_gemm() {
    const int BK = 16;
    __shared__ __align__(16) float As[BK][68];
    __shared__ __align__(16) float Bs[BK][68];

    int bm = blockIdx.x * 64;          // b offset
    int bn = blockIdx.y * 64;          // c offset
    int kb = blockIdx.z * KC;          // k chunk base
    int tid = threadIdx.x;
    int tx = tid & 15;                 // n = tx*4
    int ty = tid >> 4;                 // m = ty*4

    int lrow = tid >> 2;               // 0..63
    int lkq = (tid & 3) * 4;           // 0,4,8,12
    const float* aptr = g_MA + (size_t)(Cc + bm + lrow) * Dd + kb + lkq;
    const float* bptr = g_MA + (size_t)(bn + lrow) * Dd + kb + lkq;

    float acc[4][4];
#pragma unroll
    for (int i = 0; i < 4; i++)
#pragma unroll
        for (int j = 0; j < 4; j++) acc[i][j] = 0.f;

    float4 ra = *reinterpret_cast<const float4*>(aptr);
    float4 rb = *reinterpret_cast<const float4*>(bptr);

#pragma unroll 1
    for (int it = 0; it < KC / BK; it++) {
        As[lkq + 0][lrow] = ra.x;
        As[lkq + 1][lrow] = ra.y;
        As[lkq + 2][lrow] = ra.z;
        As[lkq + 3][lrow] = ra.w;
        Bs[lkq + 0][lrow] = rb.x;
        Bs[lkq + 1][lrow] = rb.y;
        Bs[lkq + 2][lrow] = rb.z;
        Bs[lkq + 3][lrow] = rb.w;
        __syncthreads();

        if (it + 1 < KC / BK) {
            ra = *reinterpret_cast<const float4*>(aptr + (it + 1) * BK);
            rb = *reinterpret_cast<const float4*>(bptr + (it + 1) * BK);
        }

#pragma unroll
        for (int kk = 0; kk < BK; kk++) {
            float4 a = *reinterpret_cast<const float4*>(&As[kk][ty * 4]);
            float4 b = *reinterpret_cast<const float4*>(&Bs[kk][tx * 4]);
            float av[4] = {a.x, a.y, a.z, a.w};
            float bv[4] = {b.x, b.y, b.z, b.w};
#pragma unroll
            for (int i = 0; i < 4; i++)
#pragma unroll
                for (int j = 0; j < 4; j++)
                    acc[i][j] = fmaf(av[i], bv[j], acc[i][j]);
        }
        __syncthreads();
    }

#pragma unroll
    for (int i = 0; i < 4; i++) {
        float4 v = make_float4(acc[i][0], acc[i][1], acc[i][2], acc[i][3]);
        *reinterpret_cast<float4*>(
            g_part + ((size_t)blockIdx.z * Bb + bm + ty * 4 + i) * Dd + bn + tx * 4) = v;
    }
}

// ---------------------------------------------------------------------------
// 4) Finalize: out[b,c] = -scale*(sqrt(quad+eps) + lmbda*sqrt(bd^2+eps))
//    quad = q_b + q_c - 2*sum_ks part[ks][b][c]
//    (epsilon cross-dot term eps*x.mu dropped: contributes ~2e-6 abs vs quad~1e3)
// ---------------------------------------------------------------------------
__global__ __launch_bounds__(256) void finalize(const float* __restrict__ lmbda,
                                                const float* __restrict__ scale,
                                                float* __restrict__ out) {
    int idx = blockIdx.x * 256 + threadIdx.x;
    if (idx >= Bb * Cc) return;
    int b = idx / Cc;
    int c = idx - b * Cc;
    float s = 0.f;
#pragma unroll
    for (int ks = 0; ks < KS; ks++)
        s += g_part[((size_t)ks * Bb + b) * Dd + c];
    float quad = g_q[Cc + b] + g_q[c] - 2.f * s;
    float bd = g_bd[Cc + b] - g_bd[c];
    float lm = *lmbda;
    float sc = *scale;
    out[idx] = -sc * (sqrtf(quad + 1e-6f) + lm * sqrtf(bd * bd + 1e-6f));
}

// ---------------------------------------------------------------------------
extern "C" void kernel_launch(void* const* d_in, const int* in_sizes, int n_in,
                              void* d_out, int out_size) {
    const float *x = nullptr, *mu = nullptr, *beta = nullptr, *L = nullptr;
    const float *lmbda = nullptr, *scale = nullptr;
    for (int i = 0; i < n_in; i++) {
        const float* p = (const float*)d_in[i];
        switch (in_sizes[i]) {
            case Bb * Dd:  x = p; break;
            case Cc * Dd:  mu = p; break;
            case Dd:       beta = p; break;
            case Dd * Dd:  L = p; break;
            case 1:        if (!lmbda) lmbda = p; else scale = p; break;
            default: break;
        }
    }

    gemm_ma<<<dim3((RT + 63) / 64, Dd / 64), 256>>>(x, mu, L);
    rownorm<<<RT, 256>>>(x, mu, beta);
    dot_gemm<<<dim3(Bb / 64, Dd / 64, KS), 256>>>();
    finalize<<<(Bb * Cc + 255) / 256, 256>>>(lmbda, scale, (float*)d_out);
}

// round 5
// speedup vs baseline: 3.8460x; 2.1739x over previous
#include <cuda_runtime.h>
#include <cuda_bf16.h>
#include <cstdint>
#include <stdint.h>
#include <math.h>

// Problem constants
#define Dd 1024   // feature dim
#define Cc 1000   // prototypes
#define Bb 128    // batch
#define RT 1128   // Cc + Bb stacked rows
#define MP 1152   // RT padded to multiple of 64
#define KS 8      // split-K for cross-dot gemm
#define KC (Dd / KS)

// Scratch (device globals — no allocation allowed)
__device__ __nv_bfloat16 g_Abf[MP * Dd];   // [mu; x; 0] bf16          2.25 MB
__device__ __nv_bfloat16 g_Bbf[Dd * Dd];   // tril(L)^T bf16 [n][k]    2 MB
__device__ __nv_bfloat16 g_MAbf[MP * Dd];  // MA = [mu;x] @ tril(L)    2.25 MB
__device__ float g_q[RT];                  // ||MA_r||^2 + eps*||In_r||^2
__device__ float g_bd[RT];                 // beta . In_r
__device__ float g_part[KS * Bb * Dd];     // split-K partial cross dots

// ---------------------------------------------------------------------------
// mma / ldmatrix helpers
// ---------------------------------------------------------------------------
__device__ __forceinline__ void ldsm_x4(uint32_t& r0, uint32_t& r1,
                                        uint32_t& r2, uint32_t& r3,
                                        uint32_t addr) {
    asm volatile("ldmatrix.sync.aligned.m8n8.x4.shared.b16 {%0,%1,%2,%3}, [%4];\n"
                 : "=r"(r0), "=r"(r1), "=r"(r2), "=r"(r3) : "r"(addr));
}

__device__ __forceinline__ void mma_bf16(float* d, const uint32_t* a,
                                         uint32_t b0, uint32_t b1) {
    asm volatile(
        "mma.sync.aligned.m16n8k16.row.col.f32.bf16.bf16.f32 "
        "{%0,%1,%2,%3}, {%4,%5,%6,%7}, {%8,%9}, {%0,%1,%2,%3};\n"
        : "+f"(d[0]), "+f"(d[1]), "+f"(d[2]), "+f"(d[3])
        : "r"(a[0]), "r"(a[1]), "r"(a[2]), "r"(a[3]), "r"(b0), "r"(b1));
}

// ---------------------------------------------------------------------------
// 0a) prepA: g_Abf = bf16([mu; x; zeros])
// ---------------------------------------------------------------------------
__global__ __launch_bounds__(256) void prepA(const float* __restrict__ x,
                                             const float* __restrict__ mu) {
    int idx = (blockIdx.x * 256 + threadIdx.x) * 4;
    int r = idx >> 10;
    int k = idx & (Dd - 1);
    float4 v = make_float4(0.f, 0.f, 0.f, 0.f);
    if (r < Cc)      v = *reinterpret_cast<const float4*>(mu + (size_t)r * Dd + k);
    else if (r < RT) v = *reinterpret_cast<const float4*>(x + (size_t)(r - Cc) * Dd + k);
    __nv_bfloat162 p0 = __floats2bfloat162_rn(v.x, v.y);
    __nv_bfloat162 p1 = __floats2bfloat162_rn(v.z, v.w);
    uint2 o;
    o.x = *reinterpret_cast<uint32_t*>(&p0);
    o.y = *reinterpret_cast<uint32_t*>(&p1);
    *reinterpret_cast<uint2*>(g_Abf + idx) = o;
}

// ---------------------------------------------------------------------------
// 0b) prepL: g_Bbf[n][k] = bf16( k>=n ? L[k][n] : 0 )   (tril + transpose)
// ---------------------------------------------------------------------------
__global__ void prepL(const float* __restrict__ L) {
    __shared__ float t[32][33];
    int bx = blockIdx.x * 32;  // k base
    int by = blockIdx.y * 32;  // n base
    int tx = threadIdx.x, ty = threadIdx.y;  // block (32, 8)
#pragma unroll
    for (int i = ty; i < 32; i += 8)
        t[i][tx] = L[(size_t)(bx + i) * Dd + by + tx];
    __syncthreads();
#pragma unroll
    for (int i = ty; i < 32; i += 8) {
        int n = by + i, k = bx + tx;
        float v = (k >= n) ? t[tx][i] : 0.f;
        g_Bbf[(size_t)n * Dd + k] = __float2bfloat16(v);
    }
}

// ---------------------------------------------------------------------------
// 1) gemm_ma_mma: g_MAbf[m][n] = sum_k g_Abf[m][k] * g_Bbf[n][k]  (NT, bf16 HMMA)
//    BM=BN=64, BK=32, 128 thr, 2x2 warps, warp tile 32x32.
//    Triangular skip: K starts at bn.
// ---------------------------------------------------------------------------
__global__ __launch_bounds__(128) void gemm_ma_mma() {
    __shared__ __align__(16) __nv_bfloat16 As[64][40];
    __shared__ __align__(16) __nv_bfloat16 Bs[64][40];
    int bm = blockIdx.x * 64;
    int bn = blockIdx.y * 64;
    int tid = threadIdx.x;
    int lane = tid & 31, w = tid >> 5;
    int wm = (w & 1) * 32, wn = (w >> 1) * 32;

    int lr = tid >> 1;             // 0..63 (tile row)
    int lk = (tid & 1) * 16;       // 0 / 16 (bf16 units)
    const __nv_bfloat16* aptr = g_Abf + (size_t)(bm + lr) * Dd + lk;
    const __nv_bfloat16* bptr = g_Bbf + (size_t)(bn + lr) * Dd + lk;

    float acc[2][4][4];
#pragma unroll
    for (int mt = 0; mt < 2; mt++)
#pragma unroll
        for (int nt = 0; nt < 4; nt++)
#pragma unroll
            for (int e = 0; e < 4; e++) acc[mt][nt][e] = 0.f;

    uint32_t aAddr[2], bAddr[2];
#pragma unroll
    for (int t = 0; t < 2; t++) {
        aAddr[t] = (uint32_t)__cvta_generic_to_shared(
            &As[wm + t * 16 + (lane & 15)][(lane >> 4) * 8]);
        bAddr[t] = (uint32_t)__cvta_generic_to_shared(
            &Bs[wn + t * 16 + (lane & 15)][(lane >> 4) * 8]);
    }

    int kstart = bn;  // tril skip: L^T[n][k] = 0 for k < n
    uint4 pa0 = *reinterpret_cast<const uint4*>(aptr + kstart);
    uint4 pa1 = *reinterpret_cast<const uint4*>(aptr + kstart + 8);
    uint4 pb0 = *reinterpret_cast<const uint4*>(bptr + kstart);
    uint4 pb1 = *reinterpret_cast<const uint4*>(bptr + kstart + 8);

    for (int k0 = kstart; k0 < Dd; k0 += 32) {
        *reinterpret_cast<uint4*>(&As[lr][lk]) = pa0;
        *reinterpret_cast<uint4*>(&As[lr][lk + 8]) = pa1;
        *reinterpret_cast<uint4*>(&Bs[lr][lk]) = pb0;
        *reinterpret_cast<uint4*>(&Bs[lr][lk + 8]) = pb1;
        __syncthreads();
        if (k0 + 32 < Dd) {
            pa0 = *reinterpret_cast<const uint4*>(aptr + k0 + 32);
            pa1 = *reinterpret_cast<const uint4*>(aptr + k0 + 40);
            pb0 = *reinterpret_cast<const uint4*>(bptr + k0 + 32);
            pb1 = *reinterpret_cast<const uint4*>(bptr + k0 + 40);
        }
#pragma unroll
        for (int ks = 0; ks < 2; ks++) {
            uint32_t off = (uint32_t)(ks * 32);  // bytes (16 bf16)
            uint32_t a0[4], a1[4], br0[4], br1[4];
            ldsm_x4(a0[0], a0[1], a0[2], a0[3], aAddr[0] + off);
            ldsm_x4(a1[0], a1[1], a1[2], a1[3], aAddr[1] + off);
            ldsm_x4(br0[0], br0[1], br0[2], br0[3], bAddr[0] + off);
            ldsm_x4(br1[0], br1[1], br1[2], br1[3], bAddr[1] + off);
#pragma unroll
            for (int mt = 0; mt < 2; mt++) {
                uint32_t* a = mt ? a1 : a0;
                mma_bf16(acc[mt][0], a, br0[0], br0[2]);
                mma_bf16(acc[mt][1], a, br0[1], br0[3]);
                mma_bf16(acc[mt][2], a, br1[0], br1[2]);
                mma_bf16(acc[mt][3], a, br1[1], br1[3]);
            }
        }
        __syncthreads();
    }

    int mrow = lane >> 2;
    int ncol = (lane & 3) * 2;
#pragma unroll
    for (int mt = 0; mt < 2; mt++)
#pragma unroll
        for (int nt = 0; nt < 4; nt++) {
            int row = bm + wm + mt * 16 + mrow;
            int col = bn + wn + nt * 8 + ncol;
            __nv_bfloat162 lo = __floats2bfloat162_rn(acc[mt][nt][0], acc[mt][nt][1]);
            __nv_bfloat162 hi = __floats2bfloat162_rn(acc[mt][nt][2], acc[mt][nt][3]);
            *reinterpret_cast<__nv_bfloat162*>(g_MAbf + (size_t)row * Dd + col) = lo;
            *reinterpret_cast<__nv_bfloat162*>(g_MAbf + (size_t)(row + 8) * Dd + col) = hi;
        }
}

// ---------------------------------------------------------------------------
// 2) rownorm: q_r = ||MAbf_r||^2 + 1e-6*||In_r||^2 ; bd_r = beta . In_r
// ---------------------------------------------------------------------------
__global__ __launch_bounds__(256) void rownorm(const float* __restrict__ x,
                                               const float* __restrict__ mu,
                                               const float* __restrict__ beta) {
    int r = blockIdx.x;
    const float* in = (r < Cc) ? (mu + (size_t)r * Dd) : (x + (size_t)(r - Cc) * Dd);
    const __nv_bfloat16* ma = g_MAbf + (size_t)r * Dd;
    int tid = threadIdx.x;

    uint2 u = *reinterpret_cast<const uint2*>(ma + tid * 4);
    __nv_bfloat162 m0 = *reinterpret_cast<__nv_bfloat162*>(&u.x);
    __nv_bfloat162 m1 = *reinterpret_cast<__nv_bfloat162*>(&u.y);
    float a0 = __bfloat162float(m0.x), a1 = __bfloat162float(m0.y);
    float a2 = __bfloat162float(m1.x), a3 = __bfloat162float(m1.y);
    float4 v4 = *reinterpret_cast<const float4*>(in + tid * 4);
    float4 b4 = *reinterpret_cast<const float4*>(beta + tid * 4);

    float sma = a0 * a0 + a1 * a1 + a2 * a2 + a3 * a3;
    float sin_ = v4.x * v4.x + v4.y * v4.y + v4.z * v4.z + v4.w * v4.w;
    float sb = b4.x * v4.x + b4.y * v4.y + b4.z * v4.z + b4.w * v4.w;

#pragma unroll
    for (int off = 16; off > 0; off >>= 1) {
        sma += __shfl_xor_sync(0xFFFFFFFFu, sma, off);
        sin_ += __shfl_xor_sync(0xFFFFFFFFu, sin_, off);
        sb += __shfl_xor_sync(0xFFFFFFFFu, sb, off);
    }
    __shared__ float red[3][8];
    int wid = tid >> 5, lanei = tid & 31;
    if (lanei == 0) { red[0][wid] = sma; red[1][wid] = sin_; red[2][wid] = sb; }
    __syncthreads();
    if (tid == 0) {
        float t0 = 0.f, t1 = 0.f, t2 = 0.f;
#pragma unroll
        for (int wq = 0; wq < 8; wq++) { t0 += red[0][wq]; t1 += red[1][wq]; t2 += red[2][wq]; }
        g_q[r] = t0 + 1e-6f * t1;
        g_bd[r] = t2;
    }
}

// ---------------------------------------------------------------------------
// 3) dot_mma: part[z][b][c] = sum_{k in chunk z} MAbf[Cc+b][k] * MAbf[c][k]
//    Same NT HMMA structure, split-K=8.
// ---------------------------------------------------------------------------
__global__ __launch_bounds__(128) void dot_mma() {
    __shared__ __align__(16) __nv_bfloat16 As[64][40];
    __shared__ __align__(16) __nv_bfloat16 Bs[64][40];
    int bm = blockIdx.x * 64;                // b offset
    int bn = blockIdx.y * 64;                // c offset
    int kb = blockIdx.z * KC;                // k chunk base
    int tid = threadIdx.x;
    int lane = tid & 31, w = tid >> 5;
    int wm = (w & 1) * 32, wn = (w >> 1) * 32;

    int lr = tid >> 1;
    int lk = (tid & 1) * 16;
    const __nv_bfloat16* aptr = g_MAbf + (size_t)(Cc + bm + lr) * Dd + kb + lk;
    const __nv_bfloat16* bptr = g_MAbf + (size_t)(bn + lr) * Dd + kb + lk;

    float acc[2][4][4];
#pragma unroll
    for (int mt = 0; mt < 2; mt++)
#pragma unroll
        for (int nt = 0; nt < 4; nt++)
#pragma unroll
            for (int e = 0; e < 4; e++) acc[mt][nt][e] = 0.f;

    uint32_t aAddr[2], bAddr[2];
#pragma unroll
    for (int t = 0; t < 2; t++) {
        aAddr[t] = (uint32_t)__cvta_generic_to_shared(
            &As[wm + t * 16 + (lane & 15)][(lane >> 4) * 8]);
        bAddr[t] = (uint32_t)__cvta_generic_to_shared(
            &Bs[wn + t * 16 + (lane & 15)][(lane >> 4) * 8]);
    }

    uint4 qa0 = *reinterpret_cast<const uint4*>(aptr);
    uint4 qa1 = *reinterpret_cast<const uint4*>(aptr + 8);
    uint4 qb0 = *reinterpret_cast<const uint4*>(bptr);
    uint4 qb1 = *reinterpret_cast<const uint4*>(bptr + 8);

#pragma unroll 1
    for (int k0 = 0; k0 < KC; k0 += 32) {
        *reinterpret_cast<uint4*>(&As[lr][lk]) = qa0;
        *reinterpret_cast<uint4*>(&As[lr][lk + 8]) = qa1;
        *reinterpret_cast<uint4*>(&Bs[lr][lk]) = qb0;
        *reinterpret_cast<uint4*>(&Bs[lr][lk + 8]) = qb1;
        __syncthreads();
        if (k0 + 32 < KC) {
            qa0 = *reinterpret_cast<const uint4*>(aptr + k0 + 32);
            qa1 = *reinterpret_cast<const uint4*>(aptr + k0 + 40);
            qb0 = *reinterpret_cast<const uint4*>(bptr + k0 + 32);
            qb1 = *reinterpret_cast<const uint4*>(bptr + k0 + 40);
        }
#pragma unroll
        for (int ks = 0; ks < 2; ks++) {
            uint32_t off = (uint32_t)(ks * 32);
            uint32_t a0[4], a1[4], br0[4], br1[4];
            ldsm_x4(a0[0], a0[1], a0[2], a0[3], aAddr[0] + off);
            ldsm_x4(a1[0], a1[1], a1[2], a1[3], aAddr[1] + off);
            ldsm_x4(br0[0], br0[1], br0[2], br0[3], bAddr[0] + off);
            ldsm_x4(br1[0], br1[1], br1[2], br1[3], bAddr[1] + off);
#pragma unroll
            for (int mt = 0; mt < 2; mt++) {
                uint32_t* a = mt ? a1 : a0;
                mma_bf16(acc[mt][0], a, br0[0], br0[2]);
                mma_bf16(acc[mt][1], a, br0[1], br0[3]);
                mma_bf16(acc[mt][2], a, br1[0], br1[2]);
                mma_bf16(acc[mt][3], a, br1[1], br1[3]);
            }
        }
        __syncthreads();
    }

    int mrow = lane >> 2;
    int ncol = (lane & 3) * 2;
    float* outz = g_part + (size_t)blockIdx.z * Bb * Dd;
#pragma unroll
    for (int mt = 0; mt < 2; mt++)
#pragma unroll
        for (int nt = 0; nt < 4; nt++) {
            int row = bm + wm + mt * 16 + mrow;
            int col = bn + wn + nt * 8 + ncol;
            float2 lo = make_float2(acc[mt][nt][0], acc[mt][nt][1]);
            float2 hi = make_float2(acc[mt][nt][2], acc[mt][nt][3]);
            *reinterpret_cast<float2*>(outz + (size_t)row * Dd + col) = lo;
            *reinterpret_cast<float2*>(outz + (size_t)(row + 8) * Dd + col) = hi;
        }
}

// ---------------------------------------------------------------------------
// 4) Finalize
// ---------------------------------------------------------------------------
__global__ __launch_bounds__(256) void finalize(const float* __restrict__ lmbda,
                                                const float* __restrict__ scale,
                                                float* __restrict__ out) {
    int idx = blockIdx.x * 256 + threadIdx.x;
    if (idx >= Bb * Cc) return;
    int b = idx / Cc;
    int c = idx - b * Cc;
    float s = 0.f;
#pragma unroll
    for (int ks = 0; ks < KS; ks++)
        s += g_part[((size_t)ks * Bb + b) * Dd + c];
    float quad = g_q[Cc + b] + g_q[c] - 2.f * s;
    float bd = g_bd[Cc + b] - g_bd[c];
    float lm = *lmbda;
    float sc = *scale;
    out[idx] = -sc * (sqrtf(quad + 1e-6f) + lm * sqrtf(bd * bd + 1e-6f));
}

// ---------------------------------------------------------------------------
extern "C" void kernel_launch(void* const* d_in, const int* in_sizes, int n_in,
                              void* d_out, int out_size) {
    const float *x = nullptr, *mu = nullptr, *beta = nullptr, *L = nullptr;
    const float *lmbda = nullptr, *scale = nullptr;
    for (int i = 0; i < n_in; i++) {
        const float* p = (const float*)d_in[i];
        switch (in_sizes[i]) {
            case Bb * Dd:  x = p; break;
            case Cc * Dd:  mu = p; break;
            case Dd:       beta = p; break;
            case Dd * Dd:  L = p; break;
            case 1:        if (!lmbda) lmbda = p; else scale = p; break;
            default: break;
        }
    }

    prepA<<<(MP * Dd) / (256 * 4), 256>>>(x, mu);
    prepL<<<dim3(Dd / 32, Dd / 32), dim3(32, 8)>>>(L);
    gemm_ma_mma<<<dim3(MP / 64, Dd / 64), 128>>>();
    rownorm<<<RT, 256>>>(x, mu, beta);
    dot_mma<<<dim3(Bb / 64, Dd / 64, KS), 128>>>();
    finalize<<<(Bb * Cc + 255) / 256, 256>>>(lmbda, scale, (float*)d_out);
}